// round 2
// baseline (speedup 1.0000x reference)
#include <cuda_runtime.h>
#include <cuda_bf16.h>
#include <math.h>

// Problem constants (shapes fixed by the dataset)
#define NB   32
#define NA   3
#define NH   52
#define NW   52
#define NC   80
#define MAXB 50
#define CHAN 255        // NA * (5 + NC)
#define HW   (NH * NW)  // 2704
#define INV_NB (1.0f / 32.0f)

// Anchors / STRIDE for mask [0,1,2]: [10,13,16,30,33,23] / 32
__constant__ float c_aw[3] = {0.3125f, 0.5f,     1.03125f};
__constant__ float c_ah[3] = {0.40625f, 0.9375f, 0.71875f};

// ---------------- scratch (no allocs allowed; __device__ globals) ------------
__device__ float g_x1[NB][MAXB], g_y1[NB][MAXB], g_x2[NB][MAXB], g_y2[NB][MAXB];
__device__ float g_w [NB][MAXB], g_h [NB][MAXB], g_area[NB][MAXB];
__device__ float g_tx[NB][MAXB], g_ty[NB][MAXB], g_tw[NB][MAXB], g_th[NB][MAXB];
__device__ float g_sc[NB][MAXB];
__device__ int   g_key[NB][MAXB], g_cls[NB][MAXB];
__device__ int   g_nv[NB];

__device__ __forceinline__ float sigmoidf_(float x) {
    return 1.0f / (1.0f + __expf(-x));
}
__device__ __forceinline__ float clamped_log(float p) {
    // torch-style: max(log(max(p, 1e-38)), -100)
    return fmaxf(__logf(fmaxf(p, 1e-38f)), -100.0f);
}

// ---------------- Kernel A: per-GT prep + zero the output --------------------
__global__ void prep_kernel(const float* __restrict__ tgt, float* __restrict__ out) {
    int b = blockIdx.x;
    __shared__ int s_nv;
    if (threadIdx.x == 0) {
        // cumulative validity: stop at first gx == 0
        int nv = 0;
        while (nv < MAXB && tgt[b * 250 + nv * 5 + 1] != 0.0f) nv++;
        s_nv = nv;
        g_nv[b] = nv;
        if (b == 0) { out[0] = 0.0f; out[1] = 0.0f; out[2] = 0.0f; }
    }
    __syncthreads();
    int t = threadIdx.x;
    if (t < s_nv) {
        const float* tb = tgt + b * 250 + t * 5;
        float t0 = tb[0], t1 = tb[1], t2 = tb[2], t3 = tb[3], t4 = tb[4];
        float gx = t1 * (float)NW, gy = t2 * (float)NH;
        float gw = t3 * (float)NW, gh = t4 * (float)NH;

        // best anchor: IoU of (0,0,gw,gh) vs (0,0,aw,ah) = min-overlap boxes
        int best = 0; float bestiou = -1.0f;
        #pragma unroll
        for (int a = 0; a < 3; a++) {
            float aw = c_aw[a], ah = c_ah[a];
            float inter = fminf(gw, aw) * fminf(gh, ah);
            float u = gw * gh + aw * ah - inter;
            float iou = inter / u;
            if (iou > bestiou) { bestiou = iou; best = a; }
        }
        float fgi = floorf(gx), fgj = floorf(gy);
        int gi = (int)fgi, gj = (int)fgj;
        gi = min(max(gi, 0), NW - 1);
        gj = min(max(gj, 0), NH - 1);

        g_tx[b][t] = gx - fgi;
        g_ty[b][t] = gy - fgj;
        g_tw[b][t] = logf(gw / c_aw[best]);
        g_th[b][t] = logf(gh / c_ah[best]);
        g_sc[b][t] = sqrtf(2.0f - t3 * t4);
        int c = (int)t0;
        g_cls[b][t] = min(max(c, 0), NC - 1);
        g_key[b][t] = best * HW + gj * NW + gi;

        g_x1[b][t] = gx - gw * 0.5f;  g_x2[b][t] = gx + gw * 0.5f;
        g_y1[b][t] = gy - gh * 0.5f;  g_y2[b][t] = gy + gh * 0.5f;
        g_w[b][t] = gw; g_h[b][t] = gh; g_area[b][t] = gw * gh;
    }
}

// ---------------- Kernel B: dense back-mask conf loss ------------------------
// grid: (ceil(HW/256), NB*NA), block 256. One block handles part of one (b,a) slab.
__global__ void __launch_bounds__(256) conf_kernel(const float* __restrict__ outp,
                                                   float* __restrict__ loss) {
    int slab = blockIdx.y;            // b*3 + a
    int b = slab / 3, a = slab % 3;
    int s = blockIdx.x * 256 + threadIdx.x;

    __shared__ float sx1[MAXB], sy1[MAXB], sx2[MAXB], sy2[MAXB];
    __shared__ float sw_[MAXB], sh_[MAXB], sar[MAXB];
    __shared__ int   skey[MAXB];
    __shared__ int   snv;
    if (threadIdx.x == 0) snv = g_nv[b];
    __syncthreads();
    int nv = snv;
    if (threadIdx.x < nv) {
        int t = threadIdx.x;
        sx1[t] = g_x1[b][t]; sy1[t] = g_y1[b][t];
        sx2[t] = g_x2[b][t]; sy2[t] = g_y2[b][t];
        sw_[t] = g_w[b][t];  sh_[t] = g_h[b][t];
        sar[t] = g_area[b][t]; skey[t] = g_key[b][t];
    }
    __syncthreads();

    float val = 0.0f;
    if (s < HW) {
        const float* base = outp + ((size_t)(b * CHAN + a * 85)) * HW + s;
        float lx = base[0];
        float ly = base[HW];
        float lw = base[2 * HW];
        float lh = base[3 * HW];
        float lc = base[4 * HW];

        int h = s / NW, w = s - h * NW;
        float px = sigmoidf_(lx) + (float)w;
        float py = sigmoidf_(ly) + (float)h;
        // quirk: flattened anchor index = flat/(nB*nH*nW) = slab/32
        int qa = slab >> 5;
        float pw = __expf(lw) * c_aw[qa];
        float ph = __expf(lh) * c_ah[qa];
        float px1 = px - pw * 0.5f, px2 = px + pw * 0.5f;
        float py1 = py - ph * 0.5f, py2 = py + ph * 0.5f;
        float a1 = pw * ph;
        int mykey = a * HW + s;

        bool hit = false, obj = false;
        for (int t = 0; t < nv; t++) {
            float mx = fminf(px1, sx1[t]);
            float Mx = fmaxf(px2, sx2[t]);
            float my = fminf(py1, sy1[t]);
            float My = fmaxf(py2, sy2[t]);
            float cw = (pw + sw_[t]) - (Mx - mx);
            float ch = (ph + sh_[t]) - (My - my);
            if (cw > 0.0f && ch > 0.0f) {
                float ca = cw * ch;
                // iou > 0.5  <=>  3*inter > area1 + area2   (union > 0)
                hit = hit || (3.0f * ca > a1 + sar[t]);
            }
            obj = obj || (skey[t] == mykey);
            if (hit) break;   // outcome decided: val stays 0 regardless of obj
        }
        if (!hit && !obj) {
            float pc = sigmoidf_(lc);
            val = -clamped_log(1.0f - pc);   // BCE(p, 0)
        }
    }
    // warp reduce + one atomic per warp (pre-divided by nB)
    #pragma unroll
    for (int o = 16; o > 0; o >>= 1) val += __shfl_down_sync(0xffffffffu, val, o);
    if ((threadIdx.x & 31) == 0 && val != 0.0f)
        atomicAdd(loss + 1, val * INV_NB);
}

// ---------------- Kernel C: object-cell losses (one warp per GT slot) --------
__global__ void __launch_bounds__(512) obj_kernel(const float* __restrict__ outp,
                                                  float* __restrict__ loss) {
    int gwid = (blockIdx.x * blockDim.x + threadIdx.x) >> 5;
    int lane = threadIdx.x & 31;
    if (gwid >= NB * MAXB) return;
    int b = gwid / MAXB, t = gwid % MAXB;
    int nv = g_nv[b];
    if (t >= nv) return;

    int key = g_key[b][t];
    // Am I the LAST valid writer to this cell? (sequential scatter, last wins)
    bool later = false;
    for (int t2 = t + 1 + lane; t2 < nv; t2 += 32)
        later = later || (g_key[b][t2] == key);
    if (__any_sync(0xffffffffu, later)) return;

    // Class mask = OR of class bits over ALL valid writers to this cell
    unsigned m0 = 0, m1 = 0, m2 = 0;
    for (int t2 = lane; t2 < nv; t2 += 32) {
        if (g_key[b][t2] == key) {
            int c = g_cls[b][t2];
            if (c < 32)      m0 |= 1u << c;
            else if (c < 64) m1 |= 1u << (c - 32);
            else             m2 |= 1u << (c - 64);
        }
    }
    m0 = __reduce_or_sync(0xffffffffu, m0);
    m1 = __reduce_or_sync(0xffffffffu, m1);
    m2 = __reduce_or_sync(0xffffffffu, m2);

    int a = key / HW, s = key - a * HW;
    const float* base = outp + ((size_t)(b * CHAN + a * 85)) * HW + s;

    // class BCE across 80 channels, lanes strided
    float csum = 0.0f;
    for (int c = lane; c < NC; c += 32) {
        float p = sigmoidf_(base[(size_t)(5 + c) * HW]);
        bool bit = (c < 32) ? ((m0 >> c) & 1u)
                 : (c < 64) ? ((m1 >> (c - 32)) & 1u)
                            : ((m2 >> (c - 64)) & 1u);
        csum += bit ? -clamped_log(p) : -clamped_log(1.0f - p);
    }
    #pragma unroll
    for (int o = 16; o > 0; o >>= 1) csum += __shfl_down_sync(0xffffffffu, csum, o);

    if (lane == 0) {
        float sc = g_sc[b][t];
        float sx = sigmoidf_(base[0]);
        float sy = sigmoidf_(base[HW]);
        float dx = sx - g_tx[b][t];
        float dy = sy - g_ty[b][t];
        float dw = base[2 * HW] - g_tw[b][t];
        float dh = base[3 * HW] - g_th[b][t];
        float closs = 0.5f * sc * sc * (dx * dx + dy * dy + dw * dw + dh * dh);
        float pc = sigmoidf_(base[4 * HW]);
        float confloss = -clamped_log(pc);   // BCE(p, 1) at object cell
        atomicAdd(loss + 0, closs    * INV_NB);
        atomicAdd(loss + 1, confloss * INV_NB);
        atomicAdd(loss + 2, csum     * INV_NB);
    }
}

// ---------------- launch ------------------------------------------------------
extern "C" void kernel_launch(void* const* d_in, const int* in_sizes, int n_in,
                              void* d_out, int out_size) {
    const float* output = (const float*)d_in[0];   // [32,255,52,52]
    const float* target = (const float*)d_in[1];   // [32,250]
    float* out = (float*)d_out;                    // [3]

    prep_kernel<<<NB, 64>>>(target, out);
    dim3 gridB((HW + 255) / 256, NB * NA);
    conf_kernel<<<gridB, 256>>>(output, out);
    obj_kernel<<<(NB * MAXB * 32 + 511) / 512, 512>>>(output, out);
}

// round 4
// speedup vs baseline: 1.7246x; 1.7246x over previous
#include <cuda_runtime.h>
#include <cuda_bf16.h>
#include <math.h>

// Problem constants (fixed by dataset)
#define NB   32
#define NA   3
#define NH   52
#define NW   52
#define NC   80
#define MAXB 50
#define CHAN 255
#define HW   2704          // 52*52
#define INV_NB (1.0f/32.0f)
#define G_PER_SLAB 676     // HW/4 float4 groups per (b,a) slab
#define CONF_BLOCKS (96*3) // 96 slabs x 3 parts of 256 threads
#define OBJ_BLOCKS  200    // 1600 warps / 8 warps-per-block
#define FULLM 0xffffffffu

// Anchors [10,13,16,30,33,23] / 32
__constant__ float c_aw[3] = {0.3125f,  0.5f,    1.03125f};
__constant__ float c_ah[3] = {0.40625f, 0.9375f, 0.71875f};

// ---------------- scratch (__device__ globals; no allocs allowed) ------------
__device__ float4 g_box [NB][MAXB];   // x1,y1,x2,y2
__device__ float4 g_meta[NB][MAXB];   // area, key(bits), cls(bits), 0
__device__ float4 g_tc  [NB][MAXB];   // tx,ty,tw,th
__device__ float  g_sc  [NB][MAXB];
__device__ int    g_nv  [NB];

__device__ __forceinline__ float sigmoidf_(float x) {
    return 1.0f / (1.0f + __expf(-x));
}
__device__ __forceinline__ float clamped_log(float p) {
    // torch-style: max(log(max(p,1e-38)), -100)
    return fmaxf(__logf(fmaxf(p, 1e-38f)), -100.0f);
}
// IoU>0.5 test, written with explicit intrinsics so conf & obj paths compile
// to IDENTICAL arithmetic (needed for exact cancellation of the back term).
__device__ __forceinline__ bool hit_test(float px1, float px2, float py1, float py2,
                                         float na1, const float4& bx, float ar) {
    float cw = fminf(px2, bx.z) - fmaxf(px1, bx.x);  // overlap width
    float ch = fminf(py2, bx.w) - fmaxf(py1, bx.y);  // overlap height
    // iou>0.5 <=> 3*inter > a1+a2, with overlap positivity guard
    return (fminf(cw, ch) > 0.0f) &&
           (__fmaf_rn(3.0f, __fmul_rn(cw, ch), na1) > ar);
}

// ---------------- Kernel A: per-GT prep (parallel validity scan) -------------
__global__ void prep_kernel(const float* __restrict__ tgt, float* __restrict__ out) {
    int b = blockIdx.x, t = threadIdx.x;     // 64 threads
    __shared__ unsigned s_m[2];
    float t0 = 0, t1 = 0, t2 = 0, t3 = 0, t4 = 0;
    if (t < MAXB) {
        const float* tb = tgt + b * 250 + t * 5;
        t0 = tb[0]; t1 = tb[1]; t2 = tb[2]; t3 = tb[3]; t4 = tb[4];
    }
    bool flag = (t < MAXB) && (t1 != 0.0f);
    unsigned bal = __ballot_sync(FULLM, flag);
    if ((t & 31) == 0) s_m[t >> 5] = bal;
    __syncthreads();
    unsigned m0 = s_m[0], m1 = s_m[1];
    // first invalid slot = cumulative-validity count (lanes >=50 forced invalid)
    int nv = (~m0) ? (__ffs(~m0) - 1) : (32 + __ffs(~m1) - 1);
    if (t == 0) {
        g_nv[b] = nv;
        if (b == 0) { out[0] = 0.0f; out[1] = 0.0f; out[2] = 0.0f; }
    }
    if (t < nv) {
        float gx = t1 * (float)NW, gy = t2 * (float)NH;
        float gw = t3 * (float)NW, gh = t4 * (float)NH;
        // best anchor (first-max on ties, like argmax)
        int best = 0; float bestiou = -1.0f;
        #pragma unroll
        for (int a = 0; a < 3; a++) {
            float aw = c_aw[a], ah = c_ah[a];
            float inter = fminf(gw, aw) * fminf(gh, ah);
            float iou = inter / (gw * gh + aw * ah - inter);
            if (iou > bestiou) { bestiou = iou; best = a; }
        }
        float fgi = floorf(gx), fgj = floorf(gy);
        int gi = min(max((int)fgi, 0), NW - 1);
        int gj = min(max((int)fgj, 0), NH - 1);
        int c  = min(max((int)t0, 0), NC - 1);
        int key = best * HW + gj * NW + gi;

        g_tc[b][t]  = make_float4(gx - fgi, gy - fgj,
                                  logf(gw / c_aw[best]), logf(gh / c_ah[best]));
        g_sc[b][t]  = sqrtf(2.0f - t3 * t4);
        g_box[b][t] = make_float4(gx - gw * 0.5f, gy - gh * 0.5f,
                                  gx + gw * 0.5f, gy + gh * 0.5f);
        g_meta[b][t] = make_float4(gw * gh, __int_as_float(key),
                                   __int_as_float(c), 0.0f);
    }
}

// ---------------- Kernel B: fused conf (dense) + obj (sparse) ----------------
__global__ void __launch_bounds__(256) main_kernel(const float* __restrict__ outp,
                                                   float* __restrict__ loss) {
    __shared__ float4 sbox[MAXB];
    __shared__ float  sar_[MAXB];
    __shared__ int    snv;
    __shared__ float  sacc;

    int blk = blockIdx.x;
    int tid = threadIdx.x;

    if (blk < CONF_BLOCKS) {
        // ================= dense background-conf loss =================
        int slab = blk / 3, part = blk - slab * 3;   // slab = b*3+a
        int b = slab / 3, a = slab - b * 3;
        if (tid == 0) { snv = g_nv[b]; sacc = 0.0f; }
        if (tid < MAXB) { sbox[tid] = g_box[b][tid]; sar_[tid] = g_meta[b][tid].x; }
        __syncthreads();
        int nv = snv;

        int g = part * 256 + tid;
        bool act = g < G_PER_SLAB;
        int gg = act ? g : 0;
        int s0 = gg * 4;
        int h = s0 / NW, w0 = s0 - h * NW;   // 52 % 4 == 0: group never crosses rows
        const float* base = outp + ((size_t)(b * CHAN + a * 85)) * HW + s0;
        float4 LX = *(const float4*)(base);
        float4 LY = *(const float4*)(base + HW);
        float4 LW = *(const float4*)(base + 2 * HW);
        float4 LH = *(const float4*)(base + 3 * HW);
        float4 LC = *(const float4*)(base + 4 * HW);
        int qa = slab >> 5;                   // flattening quirk anchor index
        float aw = c_aw[qa], ah = c_ah[qa];

        float lx[4] = {LX.x, LX.y, LX.z, LX.w};
        float ly[4] = {LY.x, LY.y, LY.z, LY.w};
        float lw[4] = {LW.x, LW.y, LW.z, LW.w};
        float lh[4] = {LH.x, LH.y, LH.z, LH.w};
        float lc[4] = {LC.x, LC.y, LC.z, LC.w};

        float px1[4], px2[4], py1[4], py2[4], na1[4];
        bool hit[4];
        #pragma unroll
        for (int i = 0; i < 4; i++) {
            float px = sigmoidf_(lx[i]) + (float)(w0 + i);
            float py = sigmoidf_(ly[i]) + (float)h;
            float pw = __fmul_rn(__expf(lw[i]), aw);
            float ph = __fmul_rn(__expf(lh[i]), ah);
            px1[i] = px - 0.5f * pw;  px2[i] = px + 0.5f * pw;
            py1[i] = py - 0.5f * ph;  py2[i] = py + 0.5f * ph;
            na1[i] = -__fmul_rn(pw, ph);
            hit[i] = !act;                    // inactive lanes: already decided
        }

        #pragma unroll 2
        for (int t = 0; t < nv; t++) {
            float4 bx = sbox[t];
            float  ar = sar_[t];
            #pragma unroll
            for (int i = 0; i < 4; i++)
                hit[i] = hit[i] || hit_test(px1[i], px2[i], py1[i], py2[i], na1[i], bx, ar);
            if (__all_sync(FULLM, hit[0] & hit[1] & hit[2] & hit[3])) break;
        }

        float val = 0.0f;
        if (act) {
            #pragma unroll
            for (int i = 0; i < 4; i++)
                if (!hit[i]) {
                    float pc = sigmoidf_(lc[i]);
                    val -= clamped_log(1.0f - pc);   // BCE(p,0); obj cells fixed up later
                }
        }
        #pragma unroll
        for (int o = 16; o > 0; o >>= 1) val += __shfl_down_sync(FULLM, val, o);
        if ((tid & 31) == 0 && val != 0.0f) atomicAdd(&sacc, val);
        __syncthreads();
        if (tid == 0 && sacc != 0.0f) atomicAdd(loss + 1, sacc * INV_NB);

    } else {
        // ================= sparse object-cell losses (1 warp / GT) =================
        int wid = (blk - CONF_BLOCKS) * 8 + (tid >> 5);
        int lane = tid & 31;
        if (wid >= NB * MAXB) return;
        int b = wid / MAXB, t = wid - b * MAXB;
        int nv = g_nv[b];
        if (t >= nv) return;

        float4 meta = g_meta[b][t];
        int key = __float_as_int(meta.y);
        int a = key / HW, s = key - a * HW;
        const float* base = outp + ((size_t)(b * CHAN + a * 85)) * HW + s;
        float lx = base[0], ly = base[HW], lw = base[2 * HW],
              lh = base[3 * HW], lc = base[4 * HW];
        int h = s / NW, w = s - h * NW;
        int qa = (b * 3 + a) >> 5;
        float pw = __fmul_rn(__expf(lw), c_aw[qa]);
        float ph = __fmul_rn(__expf(lh), c_ah[qa]);
        float px = sigmoidf_(lx) + (float)w;
        float py = sigmoidf_(ly) + (float)h;
        float px1 = px - 0.5f * pw, px2 = px + 0.5f * pw;
        float py1 = py - 0.5f * ph, py2 = py + 0.5f * ph;
        float na1 = -__fmul_rn(pw, ph);

        bool later = false, hit = false;
        unsigned m0 = 0, m1 = 0, m2 = 0;
        for (int t2 = lane; t2 < nv; t2 += 32) {
            float4 mt = g_meta[b][t2];
            float4 bx = g_box[b][t2];
            int k2 = __float_as_int(mt.y);
            later = later || (t2 > t && k2 == key);
            if (k2 == key) {
                int c = __float_as_int(mt.z);
                if (c < 32)      m0 |= 1u << c;
                else if (c < 64) m1 |= 1u << (c - 32);
                else             m2 |= 1u << (c - 64);
            }
            hit = hit || hit_test(px1, px2, py1, py2, na1, bx, mt.x);
        }
        if (__any_sync(FULLM, later)) return;    // only last writer survives
        hit = __any_sync(FULLM, hit);
        m0 = __reduce_or_sync(FULLM, m0);
        m1 = __reduce_or_sync(FULLM, m1);
        m2 = __reduce_or_sync(FULLM, m2);

        // class BCE across 80 channels (lanes strided)
        float csum = 0.0f;
        for (int c = lane; c < NC; c += 32) {
            float p = sigmoidf_(base[(size_t)(5 + c) * HW]);
            bool bit = (c < 32) ? ((m0 >> c) & 1u)
                     : (c < 64) ? ((m1 >> (c - 32)) & 1u)
                                : ((m2 >> (c - 64)) & 1u);
            csum += bit ? -clamped_log(p) : -clamped_log(1.0f - p);
        }
        #pragma unroll
        for (int o = 16; o > 0; o >>= 1) csum += __shfl_down_sync(FULLM, csum, o);

        if (lane == 0) {
            float4 tc = g_tc[b][t];
            float sc = g_sc[b][t];
            float dx = sigmoidf_(lx) - tc.x;
            float dy = sigmoidf_(ly) - tc.y;
            float dw = lw - tc.z;
            float dh = lh - tc.w;
            float closs = 0.5f * sc * sc * (dx * dx + dy * dy + dw * dw + dh * dh);
            float pc = sigmoidf_(lc);
            // BCE(p,1) at the object cell, plus exact removal of the
            // -log(1-pc) the conf path wrongly added when this cell wasn't hit.
            float confloss = -clamped_log(pc) + (hit ? 0.0f : clamped_log(1.0f - pc));
            atomicAdd(loss + 0, closs    * INV_NB);
            atomicAdd(loss + 1, confloss * INV_NB);
            atomicAdd(loss + 2, csum     * INV_NB);
        }
    }
}

// ---------------- launch ------------------------------------------------------
extern "C" void kernel_launch(void* const* d_in, const int* in_sizes, int n_in,
                              void* d_out, int out_size) {
    const float* output = (const float*)d_in[0];   // [32,255,52,52]
    const float* target = (const float*)d_in[1];   // [32,250]
    float* out = (float*)d_out;                    // [3]

    prep_kernel<<<NB, 64>>>(target, out);
    main_kernel<<<CONF_BLOCKS + OBJ_BLOCKS, 256>>>(output, out);
}

// round 5
// speedup vs baseline: 2.1943x; 1.2723x over previous
#include <cuda_runtime.h>
#include <cuda_bf16.h>
#include <math.h>

// Problem constants (fixed by dataset)
#define NB   32
#define NA   3
#define NH   52
#define NW   52
#define NC   80
#define MAXB 50
#define CHAN 255
#define HW   2704            // 52*52
#define INV_NB (1.0f/32.0f)
#define G_PER_SLAB 1352      // HW/2 float2 groups per (b,a) slab
#define PARTS 6              // 6*256 = 1536 >= 1352
#define CONF_BLOCKS (96*PARTS)
#define OBJ_BLOCKS  200      // 1600 warps / 8 warps-per-block
#define FULLM 0xffffffffu

// Anchors [10,13,16,30,33,23] / 32
__constant__ float c_aw[3] = {0.3125f,  0.5f,    1.03125f};
__constant__ float c_ah[3] = {0.40625f, 0.9375f, 0.71875f};

// ---------------- scratch (__device__ globals; no allocs allowed) ------------
__device__ float4 g_box [NB][MAXB];   // x1,y1,x2,y2
__device__ float4 g_meta[NB][MAXB];   // area, key(bits), cls(bits), 0
__device__ float4 g_tc  [NB][MAXB];   // tx,ty,tw,th
__device__ float  g_sc  [NB][MAXB];
__device__ int    g_nv  [NB];

__device__ __forceinline__ float sigmoidf_(float x) {
    return 1.0f / (1.0f + __expf(-x));
}
__device__ __forceinline__ float clamped_log(float p) {
    // torch-style: max(log(max(p,1e-38)), -100)
    return fmaxf(__logf(fmaxf(p, 1e-38f)), -100.0f);
}
// IoU>0.5 test; identical intrinsic sequence in conf & obj paths so the
// obj-side fixup cancels the conf-side term exactly.
__device__ __forceinline__ bool hit_test(float px1, float px2, float py1, float py2,
                                         float na1, const float4& bx, float ar) {
    float cw = fminf(px2, bx.z) - fmaxf(px1, bx.x);
    float ch = fminf(py2, bx.w) - fmaxf(py1, bx.y);
    // iou>0.5 <=> 3*inter > a1+a2, with overlap positivity guard
    return (fminf(cw, ch) > 0.0f) &&
           (__fmaf_rn(3.0f, __fmul_rn(cw, ch), na1) > ar);
}

// ---------------- Kernel A: per-GT prep (parallel validity scan) -------------
__global__ void prep_kernel(const float* __restrict__ tgt, float* __restrict__ out) {
    int b = blockIdx.x, t = threadIdx.x;     // 64 threads
    __shared__ unsigned s_m[2];
    float t0 = 0, t1 = 0, t2 = 0, t3 = 0, t4 = 0;
    if (t < MAXB) {
        const float* tb = tgt + b * 250 + t * 5;
        t0 = tb[0]; t1 = tb[1]; t2 = tb[2]; t3 = tb[3]; t4 = tb[4];
    }
    bool flag = (t < MAXB) && (t1 != 0.0f);
    unsigned bal = __ballot_sync(FULLM, flag);
    if ((t & 31) == 0) s_m[t >> 5] = bal;
    __syncthreads();
    unsigned m0 = s_m[0], m1 = s_m[1];
    int nv = (~m0) ? (__ffs(~m0) - 1) : (32 + __ffs(~m1) - 1);
    if (t == 0) {
        g_nv[b] = nv;
        if (b == 0) { out[0] = 0.0f; out[1] = 0.0f; out[2] = 0.0f; }
    }
    if (t < nv) {
        float gx = t1 * (float)NW, gy = t2 * (float)NH;
        float gw = t3 * (float)NW, gh = t4 * (float)NH;
        int best = 0; float bestiou = -1.0f;
        #pragma unroll
        for (int a = 0; a < 3; a++) {
            float aw = c_aw[a], ah = c_ah[a];
            float inter = fminf(gw, aw) * fminf(gh, ah);
            float iou = inter / (gw * gh + aw * ah - inter);
            if (iou > bestiou) { bestiou = iou; best = a; }
        }
        float fgi = floorf(gx), fgj = floorf(gy);
        int gi = min(max((int)fgi, 0), NW - 1);
        int gj = min(max((int)fgj, 0), NH - 1);
        int c  = min(max((int)t0, 0), NC - 1);
        int key = best * HW + gj * NW + gi;

        g_tc[b][t]  = make_float4(gx - fgi, gy - fgj,
                                  logf(gw / c_aw[best]), logf(gh / c_ah[best]));
        g_sc[b][t]  = sqrtf(2.0f - t3 * t4);
        g_box[b][t] = make_float4(gx - gw * 0.5f, gy - gh * 0.5f,
                                  gx + gw * 0.5f, gy + gh * 0.5f);
        g_meta[b][t] = make_float4(gw * gh, __int_as_float(key),
                                   __int_as_float(c), 0.0f);
    }
}

// ---------------- Kernel B: fused conf (dense) + obj (sparse) ----------------
__global__ void __launch_bounds__(256) main_kernel(const float* __restrict__ outp,
                                                   float* __restrict__ loss) {
    __shared__ float4 sbox[MAXB];
    __shared__ float  sar_[MAXB];
    __shared__ int    snv;
    __shared__ float  sacc;

    int blk = blockIdx.x;
    int tid = threadIdx.x;

    if (blk < CONF_BLOCKS) {
        // ================= dense background-conf loss (2 cells/thread) =========
        int slab = blk / PARTS, part = blk - slab * PARTS;   // slab = b*3+a
        int b = slab / 3, a = slab - b * 3;
        if (tid == 0) { snv = g_nv[b]; sacc = 0.0f; }
        if (tid < MAXB) { sbox[tid] = g_box[b][tid]; sar_[tid] = g_meta[b][tid].x; }
        __syncthreads();
        int nv = snv;

        int g = part * 256 + tid;
        bool act = g < G_PER_SLAB;
        int gg = act ? g : 0;
        int s0 = gg * 2;
        int h = s0 / NW, w0 = s0 - h * NW;   // 52 % 2 == 0: pair never crosses rows
        const float* base = outp + ((size_t)(b * CHAN + a * 85)) * HW + s0;
        float2 LX = *(const float2*)(base);
        float2 LY = *(const float2*)(base + HW);
        float2 LW = *(const float2*)(base + 2 * HW);
        float2 LH = *(const float2*)(base + 3 * HW);
        float2 LC = *(const float2*)(base + 4 * HW);
        int qa = slab >> 5;                   // flattening quirk anchor index
        float aw = c_aw[qa], ah = c_ah[qa];

        float lx[2] = {LX.x, LX.y}, ly[2] = {LY.x, LY.y};
        float lw[2] = {LW.x, LW.y}, lh[2] = {LH.x, LH.y};
        float lc[2] = {LC.x, LC.y};

        float px1[2], px2[2], py1[2], py2[2], na1[2];
        bool hit[2];
        #pragma unroll
        for (int i = 0; i < 2; i++) {
            float px = sigmoidf_(lx[i]) + (float)(w0 + i);
            float py = sigmoidf_(ly[i]) + (float)h;
            float pw = __fmul_rn(__expf(lw[i]), aw);
            float ph = __fmul_rn(__expf(lh[i]), ah);
            px1[i] = px - 0.5f * pw;  px2[i] = px + 0.5f * pw;
            py1[i] = py - 0.5f * ph;  py2[i] = py + 0.5f * ph;
            na1[i] = -__fmul_rn(pw, ph);
            hit[i] = false;
        }

        // hits are astronomically rare on this distribution: no early exit,
        // just a tight unrolled throughput loop.
        #pragma unroll 5
        for (int t = 0; t < nv; t++) {
            float4 bx = sbox[t];
            float  ar = sar_[t];
            hit[0] = hit[0] || hit_test(px1[0], px2[0], py1[0], py2[0], na1[0], bx, ar);
            hit[1] = hit[1] || hit_test(px1[1], px2[1], py1[1], py2[1], na1[1], bx, ar);
        }

        float val = 0.0f;
        if (act) {
            #pragma unroll
            for (int i = 0; i < 2; i++)
                if (!hit[i]) {
                    float pc = sigmoidf_(lc[i]);
                    val -= clamped_log(1.0f - pc);   // BCE(p,0); obj cells fixed up later
                }
        }
        #pragma unroll
        for (int o = 16; o > 0; o >>= 1) val += __shfl_down_sync(FULLM, val, o);
        if ((tid & 31) == 0 && val != 0.0f) atomicAdd(&sacc, val);
        __syncthreads();
        if (tid == 0 && sacc != 0.0f) atomicAdd(loss + 1, sacc * INV_NB);

    } else {
        // ================= sparse object-cell losses (1 warp / GT) =============
        int wid = (blk - CONF_BLOCKS) * 8 + (tid >> 5);
        int lane = tid & 31;
        if (wid >= NB * MAXB) return;
        int b = wid / MAXB, t = wid - b * MAXB;
        int nv = g_nv[b];
        if (t >= nv) return;

        float4 meta = g_meta[b][t];
        int key = __float_as_int(meta.y);
        int a = key / HW, s = key - a * HW;
        const float* base = outp + ((size_t)(b * CHAN + a * 85)) * HW + s;
        float lx = base[0], ly = base[HW], lw = base[2 * HW],
              lh = base[3 * HW], lc = base[4 * HW];
        int h = s / NW, w = s - h * NW;
        int qa = (b * 3 + a) >> 5;
        float pw = __fmul_rn(__expf(lw), c_aw[qa]);
        float ph = __fmul_rn(__expf(lh), c_ah[qa]);
        float px = sigmoidf_(lx) + (float)w;
        float py = sigmoidf_(ly) + (float)h;
        float px1 = px - 0.5f * pw, px2 = px + 0.5f * pw;
        float py1 = py - 0.5f * ph, py2 = py + 0.5f * ph;
        float na1 = -__fmul_rn(pw, ph);

        bool later = false, hit = false;
        unsigned m0 = 0, m1 = 0, m2 = 0;
        for (int t2 = lane; t2 < nv; t2 += 32) {
            float4 mt = g_meta[b][t2];
            float4 bx = g_box[b][t2];
            int k2 = __float_as_int(mt.y);
            later = later || (t2 > t && k2 == key);
            if (k2 == key) {
                int c = __float_as_int(mt.z);
                if (c < 32)      m0 |= 1u << c;
                else if (c < 64) m1 |= 1u << (c - 32);
                else             m2 |= 1u << (c - 64);
            }
            hit = hit || hit_test(px1, px2, py1, py2, na1, bx, mt.x);
        }
        if (__any_sync(FULLM, later)) return;    // only last writer survives
        hit = __any_sync(FULLM, hit);
        m0 = __reduce_or_sync(FULLM, m0);
        m1 = __reduce_or_sync(FULLM, m1);
        m2 = __reduce_or_sync(FULLM, m2);

        // class BCE across 80 channels (lanes strided)
        float csum = 0.0f;
        for (int c = lane; c < NC; c += 32) {
            float p = sigmoidf_(base[(size_t)(5 + c) * HW]);
            bool bit = (c < 32) ? ((m0 >> c) & 1u)
                     : (c < 64) ? ((m1 >> (c - 32)) & 1u)
                                : ((m2 >> (c - 64)) & 1u);
            csum += bit ? -clamped_log(p) : -clamped_log(1.0f - p);
        }
        #pragma unroll
        for (int o = 16; o > 0; o >>= 1) csum += __shfl_down_sync(FULLM, csum, o);

        if (lane == 0) {
            float4 tc = g_tc[b][t];
            float sc = g_sc[b][t];
            float dx = sigmoidf_(lx) - tc.x;
            float dy = sigmoidf_(ly) - tc.y;
            float dw = lw - tc.z;
            float dh = lh - tc.w;
            float closs = 0.5f * sc * sc * (dx * dx + dy * dy + dw * dw + dh * dh);
            float pc = sigmoidf_(lc);
            // BCE(p,1) at the object cell, plus exact removal of the
            // -log(1-pc) the conf path wrongly added when this cell wasn't hit.
            float confloss = -clamped_log(pc) + (hit ? 0.0f : clamped_log(1.0f - pc));
            atomicAdd(loss + 0, closs    * INV_NB);
            atomicAdd(loss + 1, confloss * INV_NB);
            atomicAdd(loss + 2, csum     * INV_NB);
        }
    }
}

// ---------------- launch ------------------------------------------------------
extern "C" void kernel_launch(void* const* d_in, const int* in_sizes, int n_in,
                              void* d_out, int out_size) {
    const float* output = (const float*)d_in[0];   // [32,255,52,52]
    const float* target = (const float*)d_in[1];   // [32,250]
    float* out = (float*)d_out;                    // [3]

    prep_kernel<<<NB, 64>>>(target, out);
    main_kernel<<<CONF_BLOCKS + OBJ_BLOCKS, 256>>>(output, out);
}

// round 7
// speedup vs baseline: 2.5870x; 1.1789x over previous
#include <cuda_runtime.h>
#include <cuda_bf16.h>
#include <math.h>

// Problem constants (fixed by dataset)
#define NB   32
#define NA   3
#define NH   52
#define NW   52
#define NC   80
#define MAXB 50
#define CHAN 255
#define HW   2704            // 52*52
#define INV_NB (1.0f/32.0f)
#define G_PER_SLAB 1352      // HW/2 float2 groups per (b,a) slab
#define PARTS 6              // 6*256 = 1536 >= 1352
#define CONF_BLOCKS (96*PARTS)
#define OBJ_BLOCKS  200      // 1600 warps / 8 warps-per-block
#define FULLM 0xffffffffu

// Anchors [10,13,16,30,33,23] / 32
__constant__ float c_aw[3] = {0.3125f,  0.5f,    1.03125f};
__constant__ float c_ah[3] = {0.40625f, 0.9375f, 0.71875f};

__device__ __forceinline__ float sigmoidf_(float x) {
    return 1.0f / (1.0f + __expf(-x));
}
__device__ __forceinline__ float clamped_log(float p) {
    // torch-style: max(log(max(p,1e-38)), -100)
    return fmaxf(__logf(fmaxf(p, 1e-38f)), -100.0f);
}
// IoU>0.5 test; identical intrinsic sequence in conf & obj paths so the
// obj-side fixup cancels the conf-side term exactly.
__device__ __forceinline__ bool hit_test(float px1, float px2, float py1, float py2,
                                         float na1, const float4& bx, float ar) {
    float cw = fminf(px2, bx.z) - fmaxf(px1, bx.x);
    float ch = fminf(py2, bx.w) - fmaxf(py1, bx.y);
    // iou>0.5 <=> 3*inter > a1+a2, with overlap positivity guard
    return (fminf(cw, ch) > 0.0f) &&
           (__fmaf_rn(3.0f, __fmul_rn(cw, ch), na1) > ar);
}
__device__ __forceinline__ int best_anchor(float gw, float gh) {
    int best = 0; float bi = -1.0f;
    #pragma unroll
    for (int a = 0; a < 3; a++) {
        float aw = c_aw[a], ah = c_ah[a];
        float inter = fminf(gw, aw) * fminf(gh, ah);
        float iou = inter / (gw * gh + aw * ah - inter);
        if (iou > bi) { bi = iou; best = a; }
    }
    return best;
}

__global__ void __launch_bounds__(256) main_kernel(const float* __restrict__ outp,
                                                   const float* __restrict__ tgt,
                                                   float* __restrict__ loss) {
    __shared__ float4 sboxR[MAXB]; __shared__ float sarR[MAXB];   // raw GT boxes
    __shared__ float4 sboxC[MAXB]; __shared__ float sarC[MAXB];   // area-pruned
    __shared__ unsigned s_m[2];
    __shared__ float swm[8];
    __shared__ int   snv, scnt;
    __shared__ float sthr, sacc;

    int blk = blockIdx.x;
    int tid = threadIdx.x;

    if (blk < CONF_BLOCKS) {
        // ============ dense background-conf loss (2 cells/thread) ============
        int slab = blk / PARTS, part = blk - slab * PARTS;  // slab = b*3+a
        int b = slab / 3, a = slab - b * 3;
        const float* tb = tgt + b * 250;

        // --- GT prologue: validity ballot + raw boxes (warps 0,1) ---
        if (tid < 64) {
            float t1 = 0, t2 = 0, t3 = 0, t4 = 0;
            if (tid < MAXB) {
                const float* p = tb + tid * 5;
                t1 = p[1]; t2 = p[2]; t3 = p[3]; t4 = p[4];
            }
            bool flag = (tid < MAXB) && (t1 != 0.0f);
            unsigned bal = __ballot_sync(FULLM, flag);
            if ((tid & 31) == 0) s_m[tid >> 5] = bal;
            if (tid < MAXB) {
                float gx = t1 * 52.0f, gy = t2 * 52.0f;
                float gw = t3 * 52.0f, gh = t4 * 52.0f;
                sboxR[tid] = make_float4(gx - gw * 0.5f, gy - gh * 0.5f,
                                         gx + gw * 0.5f, gy + gh * 0.5f);
                sarR[tid] = gw * gh;
            }
        }
        if (tid == 0) { scnt = 0; sacc = 0.0f; }

        // --- per-cell pred boxes ---
        int g = part * 256 + tid;
        bool act = g < G_PER_SLAB;
        int gg = act ? g : 0;
        int s0 = gg * 2;
        int h = s0 / NW, w0 = s0 - h * NW;   // pair never crosses a row (52 even)
        const float* base = outp + ((size_t)(b * CHAN + a * 85)) * HW + s0;
        float2 LX = *(const float2*)(base);
        float2 LY = *(const float2*)(base + HW);
        float2 LW = *(const float2*)(base + 2 * HW);
        float2 LH = *(const float2*)(base + 3 * HW);
        float2 LC = *(const float2*)(base + 4 * HW);
        int qa = slab >> 5;                   // flattening quirk anchor index
        float aw = c_aw[qa], ah = c_ah[qa];

        float lx[2] = {LX.x, LX.y}, ly[2] = {LY.x, LY.y};
        float lw[2] = {LW.x, LW.y}, lh[2] = {LH.x, LH.y};
        float lc[2] = {LC.x, LC.y};
        float px1[2], px2[2], py1[2], py2[2], na1[2], a1[2];
        #pragma unroll
        for (int i = 0; i < 2; i++) {
            float px = sigmoidf_(lx[i]) + (float)(w0 + i);
            float py = sigmoidf_(ly[i]) + (float)h;
            float pw = __fmul_rn(__expf(lw[i]), aw);
            float ph = __fmul_rn(__expf(lh[i]), ah);
            px1[i] = px - 0.5f * pw;  px2[i] = px + 0.5f * pw;
            py1[i] = py - 0.5f * ph;  py2[i] = py + 0.5f * ph;
            a1[i]  = __fmul_rn(pw, ph);
            na1[i] = -a1[i];
        }

        // --- block max of pred areas -> prune threshold ---
        float amax = fmaxf(a1[0], a1[1]);
        #pragma unroll
        for (int o = 16; o > 0; o >>= 1)
            amax = fmaxf(amax, __shfl_xor_sync(FULLM, amax, o));
        if ((tid & 31) == 0) swm[tid >> 5] = amax;
        __syncthreads();
        if (tid == 0) {
            float m = swm[0];
            #pragma unroll
            for (int i = 1; i < 8; i++) m = fmaxf(m, swm[i]);
            sthr = 2.0f * m;                  // GT with area >= 2*amax cannot hit
            unsigned mm0 = s_m[0], mm1 = s_m[1];
            snv = (~mm0) ? (__ffs(~mm0) - 1) : (32 + __ffs(~mm1) - 1);
        }
        __syncthreads();
        int nv = snv; float thr = sthr;

        // --- compact GT list (order irrelevant: OR of hits) ---
        if (tid < nv && sarR[tid] < thr) {
            int idx = atomicAdd(&scnt, 1);
            sboxC[idx] = sboxR[tid]; sarC[idx] = sarR[tid];
        }
        __syncthreads();
        int cnt = scnt;

        bool hit0 = false, hit1 = false;
        #pragma unroll 4
        for (int t = 0; t < cnt; t++) {
            float4 bx = sboxC[t]; float ar = sarC[t];
            hit0 = hit0 || hit_test(px1[0], px2[0], py1[0], py2[0], na1[0], bx, ar);
            hit1 = hit1 || hit_test(px1[1], px2[1], py1[1], py2[1], na1[1], bx, ar);
        }

        float val = 0.0f;
        if (act) {
            if (!hit0) val -= clamped_log(1.0f - sigmoidf_(lc[0]));
            if (!hit1) val -= clamped_log(1.0f - sigmoidf_(lc[1]));
        }
        #pragma unroll
        for (int o = 16; o > 0; o >>= 1) val += __shfl_down_sync(FULLM, val, o);
        if ((tid & 31) == 0 && val != 0.0f) atomicAdd(&sacc, val);
        __syncthreads();
        if (tid == 0 && sacc != 0.0f) atomicAdd(loss + 1, sacc * INV_NB);

    } else {
        // ============ sparse object-cell losses (1 warp / GT slot) ============
        int wid2 = (blk - CONF_BLOCKS) * 8 + (tid >> 5);
        int lane = tid & 31;
        if (wid2 >= NB * MAXB) return;
        int b = wid2 / MAXB, t = wid2 - b * MAXB;
        const float* tb = tgt + b * 250;

        bool f0 = tb[lane * 5 + 1] != 0.0f;
        bool f1 = (lane < MAXB - 32) && (tb[(lane + 32) * 5 + 1] != 0.0f);
        unsigned m0b = __ballot_sync(FULLM, f0);
        unsigned m1b = __ballot_sync(FULLM, f1);
        int nv = (~m0b) ? (__ffs(~m0b) - 1) : (32 + __ffs(~m1b) - 1);
        if (t >= nv) return;

        // own slot (computed redundantly on all lanes; broadcast loads)
        float o0 = tb[t * 5], o1 = tb[t * 5 + 1], o2 = tb[t * 5 + 2],
              o3 = tb[t * 5 + 3], o4 = tb[t * 5 + 4];
        float gx = o1 * 52.0f, gy = o2 * 52.0f, gw = o3 * 52.0f, gh = o4 * 52.0f;
        int best = best_anchor(gw, gh);
        float fgi = floorf(gx), fgj = floorf(gy);
        int gi = min(max((int)fgi, 0), NW - 1);
        int gj = min(max((int)fgj, 0), NH - 1);
        int key = best * HW + gj * NW + gi;
        int a = best, s = gj * NW + gi;

        const float* base = outp + ((size_t)(b * CHAN + a * 85)) * HW + s;
        float lx = base[0], ly = base[HW], lw = base[2 * HW],
              lh = base[3 * HW], lc = base[4 * HW];
        int qa = (b * 3 + a) >> 5;
        float pw = __fmul_rn(__expf(lw), c_aw[qa]);
        float ph = __fmul_rn(__expf(lh), c_ah[qa]);
        float px = sigmoidf_(lx) + (float)gi;
        float py = sigmoidf_(ly) + (float)gj;
        float px1 = px - 0.5f * pw, px2 = px + 0.5f * pw;
        float py1 = py - 0.5f * ph, py2 = py + 0.5f * ph;
        float na1 = -__fmul_rn(pw, ph);

        bool later = false, hit = false;
        unsigned cm0 = 0, cm1 = 0, cm2 = 0;
        for (int t2 = lane; t2 < nv; t2 += 32) {
            const float* sp = tb + t2 * 5;
            float u0 = sp[0], u1 = sp[1], u2 = sp[2], u3 = sp[3], u4 = sp[4];
            float hx = u1 * 52.0f, hy = u2 * 52.0f;
            float hw_ = u3 * 52.0f, hh = u4 * 52.0f;
            int b2 = best_anchor(hw_, hh);
            float f2i = floorf(hx), f2j = floorf(hy);
            int gi2 = min(max((int)f2i, 0), NW - 1);
            int gj2 = min(max((int)f2j, 0), NH - 1);
            int key2 = b2 * HW + gj2 * NW + gi2;
            later = later || (t2 > t && key2 == key);
            if (key2 == key) {
                int c = min(max((int)u0, 0), NC - 1);
                if (c < 32)      cm0 |= 1u << c;
                else if (c < 64) cm1 |= 1u << (c - 32);
                else             cm2 |= 1u << (c - 64);
            }
            float4 bx = make_float4(hx - hw_ * 0.5f, hy - hh * 0.5f,
                                    hx + hw_ * 0.5f, hy + hh * 0.5f);
            hit = hit || hit_test(px1, px2, py1, py2, na1, bx, hw_ * hh);
        }
        if (__any_sync(FULLM, later)) return;    // only last writer survives
        hit = __any_sync(FULLM, hit);
        cm0 = __reduce_or_sync(FULLM, cm0);
        cm1 = __reduce_or_sync(FULLM, cm1);
        cm2 = __reduce_or_sync(FULLM, cm2);

        // class BCE across 80 channels (lanes strided)
        float csum = 0.0f;
        for (int c = lane; c < NC; c += 32) {
            float p = sigmoidf_(base[(size_t)(5 + c) * HW]);
            bool bit = (c < 32) ? ((cm0 >> c) & 1u)
                     : (c < 64) ? ((cm1 >> (c - 32)) & 1u)
                                : ((cm2 >> (c - 64)) & 1u);
            csum += bit ? -clamped_log(p) : -clamped_log(1.0f - p);
        }
        #pragma unroll
        for (int o = 16; o > 0; o >>= 1) csum += __shfl_down_sync(FULLM, csum, o);

        if (lane == 0) {
            float tx = gx - fgi, ty = gy - fgj;
            float tw = logf(gw / c_aw[best]);
            float th = logf(gh / c_ah[best]);
            float sc = sqrtf(2.0f - o3 * o4);
            float dx = sigmoidf_(lx) - tx;
            float dy = sigmoidf_(ly) - ty;
            float dw = lw - tw;
            float dh = lh - th;
            float closs = 0.5f * sc * sc * (dx * dx + dy * dy + dw * dw + dh * dh);
            float pc = sigmoidf_(lc);
            // BCE(p,1) at the object cell, plus exact removal of the
            // -log(1-pc) the conf path wrongly added when this cell wasn't hit.
            float confloss = -clamped_log(pc) + (hit ? 0.0f : clamped_log(1.0f - pc));
            atomicAdd(loss + 0, closs    * INV_NB);
            atomicAdd(loss + 1, confloss * INV_NB);
            atomicAdd(loss + 2, csum     * INV_NB);
        }
    }
}

// ---------------- launch ------------------------------------------------------
extern "C" void kernel_launch(void* const* d_in, const int* in_sizes, int n_in,
                              void* d_out, int out_size) {
    const float* output = (const float*)d_in[0];   // [32,255,52,52]
    const float* target = (const float*)d_in[1];   // [32,250]
    float* out = (float*)d_out;                    // [3]

    cudaMemsetAsync(out, 0, 3 * sizeof(float), 0);
    main_kernel<<<CONF_BLOCKS + OBJ_BLOCKS, 256>>>(output, target, out);
}